// round 1
// baseline (speedup 1.0000x reference)
#include <cuda_runtime.h>
#include <cuda_bf16.h>

#define N_NODES 50000
#define N_EDGES 800000
#define E_TOT   (N_EDGES + N_NODES)   // 850000 (self-loops appended)
#define F_IN    128
#define HEADS   4
#define C1      32
#define C2      128
#define D1      (HEADS * C1)          // 128
#define D2      (HEADS * C2)          // 512
#define OUT_DIM 2
#define NEG_SLOPE 0.2f
#define NEG_INF  (-3.402823466e38f)

// ---------------- device scratch (static allocation; no cudaMalloc allowed) ----
__device__ float g_xl1[N_NODES * D1];
__device__ float g_xr1[N_NODES * D1];
__device__ float g_acc1[N_NODES * D1];
__device__ float g_h1[N_NODES * D1];
__device__ float g_xl2[N_NODES * D2];
__device__ float g_xr2[N_NODES * D2];
__device__ float g_acc2[N_NODES * D2];
__device__ float g_hout[N_NODES * C2];
__device__ float g_e[E_TOT * HEADS];
__device__ float g_emax[N_NODES * HEADS];
__device__ float g_denom[N_NODES * HEADS];
__device__ int   g_src[E_TOT];
__device__ int   g_dst[E_TOT];
__device__ int   g_is64;

// ---------------- helpers ------------------------------------------------------
__device__ __forceinline__ void atomicMaxFloat(float* addr, float val) {
    int* ia = (int*)addr;
    int old = *ia;
    while (__int_as_float(old) < val) {
        int assumed = old;
        old = atomicCAS(ia, assumed, __float_as_int(val));
        if (old == assumed) break;
    }
}

// ---------------- dtype detection for edge_index -------------------------------
// int64 values in [0, 50000): every odd 32-bit word is 0. For int32, odd words
// are random node ids -> essentially surely nonzero among 512 samples.
__global__ void detect_dtype_kernel(const int* __restrict__ ei32) {
    int nz = 0;
    for (int i = threadIdx.x; i < 512; i += blockDim.x) nz |= ei32[2 * i + 1];
    nz = __syncthreads_or(nz);
    if (threadIdx.x == 0) g_is64 = (nz == 0) ? 1 : 0;
}

__global__ void build_edges_kernel(const void* __restrict__ ei) {
    int i = blockIdx.x * blockDim.x + threadIdx.x;
    if (i >= E_TOT) return;
    if (i < N_EDGES) {
        if (g_is64) {
            const long long* p = (const long long*)ei;
            g_src[i] = (int)p[i];
            g_dst[i] = (int)p[N_EDGES + i];
        } else {
            const int* p = (const int*)ei;
            g_src[i] = p[i];
            g_dst[i] = p[N_EDGES + i];
        }
    } else {
        int n = i - N_EDGES;
        g_src[i] = n;
        g_dst[i] = n;
    }
}

__global__ void fill_kernel(float* __restrict__ p, float v, int n) {
    int i = blockIdx.x * blockDim.x + threadIdx.x;
    if (i < n) p[i] = v;
}

// ---------------- classic 64x64 tiled SGEMM (C = A[NxK] @ B[KxM]) --------------
// K multiple of 16 and >= 16; M multiple of 64. N guarded.
__global__ void sgemm_nn(const float* __restrict__ A, const float* __restrict__ B,
                         float* __restrict__ C, int N, int K, int M) {
    __shared__ float As[16][65];
    __shared__ float Bs[16][64];
    const int tx = threadIdx.x & 15;
    const int ty = threadIdx.x >> 4;
    const int n0 = blockIdx.y * 64;
    const int m0 = blockIdx.x * 64;

    float acc[4][4] = {};

    for (int k0 = 0; k0 < K; k0 += 16) {
        // A tile: 64 rows x 16 cols, float4 per thread, stored transposed
        {
            int r = threadIdx.x >> 2;          // 0..63
            int c = (threadIdx.x & 3) * 4;     // 0,4,8,12
            int gr = n0 + r;
            float4 v = make_float4(0.f, 0.f, 0.f, 0.f);
            if (gr < N) v = *(const float4*)(A + (size_t)gr * K + k0 + c);
            As[c + 0][r] = v.x; As[c + 1][r] = v.y;
            As[c + 2][r] = v.z; As[c + 3][r] = v.w;
        }
        // B tile: 16 rows x 64 cols
        {
            int r = threadIdx.x >> 4;          // 0..15
            int c = (threadIdx.x & 15) * 4;    // 0..60
            float4 v = *(const float4*)(B + (size_t)(k0 + r) * M + m0 + c);
            *(float4*)&Bs[r][c] = v;
        }
        __syncthreads();

        #pragma unroll
        for (int kk = 0; kk < 16; kk++) {
            float a[4], b[4];
            #pragma unroll
            for (int i = 0; i < 4; i++) a[i] = As[kk][ty * 4 + i];
            #pragma unroll
            for (int j = 0; j < 4; j++) b[j] = Bs[kk][tx * 4 + j];
            #pragma unroll
            for (int i = 0; i < 4; i++)
                #pragma unroll
                for (int j = 0; j < 4; j++)
                    acc[i][j] += a[i] * b[j];
        }
        __syncthreads();
    }

    #pragma unroll
    for (int i = 0; i < 4; i++) {
        int gr = n0 + ty * 4 + i;
        if (gr < N) {
            #pragma unroll
            for (int j = 0; j < 4; j++)
                C[(size_t)gr * M + m0 + tx * 4 + j] = acc[i][j];
        }
    }
}

// ---------------- edge kernels --------------------------------------------------
// thread = (edge, head). e = sum(leaky_relu(xl[src]+xr[dst]) * att); atomic max.
template <int C>
__global__ void edge_scores_kernel(const float* __restrict__ xl,
                                   const float* __restrict__ xr,
                                   const float* __restrict__ att) {
    int idx = blockIdx.x * blockDim.x + threadIdx.x;
    if (idx >= E_TOT * HEADS) return;
    int e = idx >> 2, h = idx & 3;
    int s = g_src[e], d = g_dst[e];
    const float4* pl = (const float4*)(xl + (size_t)s * HEADS * C + h * C);
    const float4* pr = (const float4*)(xr + (size_t)d * HEADS * C + h * C);
    const float4* pa = (const float4*)(att + h * C);
    float acc = 0.f;
    #pragma unroll
    for (int c = 0; c < C / 4; c++) {
        float4 l = pl[c], r = pr[c], a = pa[c];
        float m;
        m = l.x + r.x; acc += (m > 0.f ? m : NEG_SLOPE * m) * a.x;
        m = l.y + r.y; acc += (m > 0.f ? m : NEG_SLOPE * m) * a.y;
        m = l.z + r.z; acc += (m > 0.f ? m : NEG_SLOPE * m) * a.z;
        m = l.w + r.w; acc += (m > 0.f ? m : NEG_SLOPE * m) * a.w;
    }
    g_e[idx] = acc;
    atomicMaxFloat(&g_emax[d * HEADS + h], acc);
}

__global__ void edge_exp_kernel() {
    int idx = blockIdx.x * blockDim.x + threadIdx.x;
    if (idx >= E_TOT * HEADS) return;
    int e = idx >> 2, h = idx & 3;
    int d = g_dst[e];
    float ex = __expf(g_e[idx] - g_emax[d * HEADS + h]);
    g_e[idx] = ex;
    atomicAdd(&g_denom[d * HEADS + h], ex);
}

template <int C>
__global__ void edge_aggregate_kernel(const float* __restrict__ xl,
                                      float* __restrict__ acc) {
    int idx = blockIdx.x * blockDim.x + threadIdx.x;
    if (idx >= E_TOT * HEADS) return;
    int e = idx >> 2, h = idx & 3;
    int s = g_src[e], d = g_dst[e];
    float alpha = g_e[idx] / g_denom[d * HEADS + h];
    const float4* pl = (const float4*)(xl + (size_t)s * HEADS * C + h * C);
    float* po = acc + (size_t)d * HEADS * C + h * C;
    #pragma unroll
    for (int c = 0; c < C / 4; c++) {
        float4 v = pl[c];
        atomicAdd(po + 4 * c + 0, alpha * v.x);
        atomicAdd(po + 4 * c + 1, alpha * v.y);
        atomicAdd(po + 4 * c + 2, alpha * v.z);
        atomicAdd(po + 4 * c + 3, alpha * v.w);
    }
}

// ---------------- finalize / decoder --------------------------------------------
__global__ void finalize1_kernel(const float* __restrict__ b1) {
    int i = blockIdx.x * blockDim.x + threadIdx.x;
    if (i >= N_NODES * D1) return;
    float v = g_acc1[i] + b1[i & (D1 - 1)];
    g_h1[i] = v > 0.f ? v : 0.f;
}

__global__ void finalize2_kernel(const float* __restrict__ b2, float* __restrict__ hout) {
    int i = blockIdx.x * blockDim.x + threadIdx.x;
    if (i >= N_NODES * C2) return;
    int n = i >> 7, c = i & (C2 - 1);
    const float* p = g_acc2 + (size_t)n * D2 + c;
    float v = (p[0] + p[C2] + p[2 * C2] + p[3 * C2]) * 0.25f + b2[c];
    g_hout[i] = v;
    if (hout) hout[i] = v;
}

__global__ void decoder_kernel(const float* __restrict__ Wo, const float* __restrict__ bo,
                               float* __restrict__ outp) {
    int n = blockIdx.x * blockDim.x + threadIdx.x;
    if (n >= N_NODES) return;
    const float* h = g_hout + (size_t)n * C2;
    float a0 = bo[0], a1 = bo[1];
    #pragma unroll 8
    for (int c = 0; c < C2; c++) {
        float v = h[c];
        a0 += v * Wo[2 * c];
        a1 += v * Wo[2 * c + 1];
    }
    outp[2 * n + 0] = a0;
    outp[2 * n + 1] = a1;
}

// ---------------- launch ---------------------------------------------------------
static inline int cdiv(int a, int b) { return (a + b - 1) / b; }

extern "C" void kernel_launch(void* const* d_in, const int* in_sizes, int n_in,
                              void* d_out, int out_size) {
    const float* x    = (const float*)d_in[0];
    const void*  ei   = d_in[1];
    const float* Wl1  = (const float*)d_in[2];
    const float* Wr1  = (const float*)d_in[3];
    const float* att1 = (const float*)d_in[4];
    const float* b1   = (const float*)d_in[5];
    const float* Wl2  = (const float*)d_in[6];
    const float* Wr2  = (const float*)d_in[7];
    const float* att2 = (const float*)d_in[8];
    const float* b2   = (const float*)d_in[9];
    const float* Wo   = (const float*)d_in[10];
    const float* bo   = (const float*)d_in[11];

    float* outf = (float*)d_out;
    // reference returns (out, h): assume [out | h] when both fit.
    float* outp = nullptr;
    float* hp   = nullptr;
    if (out_size >= N_NODES * (OUT_DIM + C2)) { outp = outf; hp = outf + (size_t)N_NODES * OUT_DIM; }
    else if (out_size == N_NODES * C2)        { hp = outf; }
    else                                       { outp = outf; }

    // resolve device scratch addresses (host side; no alloc)
    float *xl1, *xr1, *acc1, *xl2, *xr2, *acc2, *emax, *denom;
    cudaGetSymbolAddress((void**)&xl1,   g_xl1);
    cudaGetSymbolAddress((void**)&xr1,   g_xr1);
    cudaGetSymbolAddress((void**)&acc1,  g_acc1);
    cudaGetSymbolAddress((void**)&xl2,   g_xl2);
    cudaGetSymbolAddress((void**)&xr2,   g_xr2);
    cudaGetSymbolAddress((void**)&acc2,  g_acc2);
    cudaGetSymbolAddress((void**)&emax,  g_emax);
    cudaGetSymbolAddress((void**)&denom, g_denom);
    float *h1; cudaGetSymbolAddress((void**)&h1, g_h1);

    const int T = 256;
    const int EH = E_TOT * HEADS;

    // 0) edge index dtype + edge list (with self-loops)
    detect_dtype_kernel<<<1, 256>>>((const int*)ei);
    build_edges_kernel<<<cdiv(E_TOT, T), T>>>(ei);

    // ---------------- layer 1 ----------------
    {
        dim3 g(D1 / 64, cdiv(N_NODES, 64));
        sgemm_nn<<<g, 256>>>(x, Wl1, xl1, N_NODES, F_IN, D1);
        sgemm_nn<<<g, 256>>>(x, Wr1, xr1, N_NODES, F_IN, D1);
    }
    fill_kernel<<<cdiv(N_NODES * HEADS, T), T>>>(emax, NEG_INF, N_NODES * HEADS);
    fill_kernel<<<cdiv(N_NODES * HEADS, T), T>>>(denom, 0.f, N_NODES * HEADS);
    fill_kernel<<<cdiv(N_NODES * D1, T), T>>>(acc1, 0.f, N_NODES * D1);

    edge_scores_kernel<C1><<<cdiv(EH, T), T>>>(xl1, xr1, att1);
    edge_exp_kernel<<<cdiv(EH, T), T>>>();
    edge_aggregate_kernel<C1><<<cdiv(EH, T), T>>>(xl1, acc1);
    finalize1_kernel<<<cdiv(N_NODES * D1, T), T>>>(b1);

    // ---------------- layer 2 ----------------
    {
        dim3 g(D2 / 64, cdiv(N_NODES, 64));
        sgemm_nn<<<g, 256>>>(h1, Wl2, xl2, N_NODES, D1, D2);
        sgemm_nn<<<g, 256>>>(h1, Wr2, xr2, N_NODES, D1, D2);
    }
    fill_kernel<<<cdiv(N_NODES * HEADS, T), T>>>(emax, NEG_INF, N_NODES * HEADS);
    fill_kernel<<<cdiv(N_NODES * HEADS, T), T>>>(denom, 0.f, N_NODES * HEADS);
    fill_kernel<<<cdiv(N_NODES * D2, T), T>>>(acc2, 0.f, N_NODES * D2);

    edge_scores_kernel<C2><<<cdiv(EH, T), T>>>(xl2, xr2, att2);
    edge_exp_kernel<<<cdiv(EH, T), T>>>();
    edge_aggregate_kernel<C2><<<cdiv(EH, T), T>>>(xl2, acc2);
    finalize2_kernel<<<cdiv(N_NODES * C2, T), T>>>(b2, hp);

    if (outp) decoder_kernel<<<cdiv(N_NODES, T), T>>>(Wo, bo, outp);
}

// round 2
// speedup vs baseline: 4.5362x; 4.5362x over previous
#include <cuda_runtime.h>
#include <cuda_bf16.h>

#define N_NODES 50000
#define N_EDGES 800000
#define E_TOT   (N_EDGES + N_NODES)   // 850000 (self-loops appended)
#define F_IN    128
#define HEADS   4
#define C1      32
#define C2      128
#define D1      (HEADS * C1)          // 128
#define D2      (HEADS * C2)          // 512
#define OUT_DIM 2
#define NEG_SLOPE 0.2f
#define NEG_INF  (-3.402823466e38f)

// ---------------- device scratch (static; no cudaMalloc allowed) ---------------
__device__ float g_xl1[N_NODES * D1];
__device__ float g_xr1[N_NODES * D1];
__device__ float g_h1[N_NODES * D1];
__device__ float g_xl2[N_NODES * D2];
__device__ float g_xr2[N_NODES * D2];
__device__ float g_hout[N_NODES * C2];
__device__ int   g_src[E_TOT];
__device__ int   g_dst[E_TOT];
__device__ int   g_deg[N_NODES];
__device__ int   g_rowptr[N_NODES + 1];
__device__ int   g_cursor[N_NODES];
__device__ int   g_csr_src[E_TOT];
__device__ int   g_is64;

// ---------------- dtype detection for edge_index -------------------------------
// int64 values in [0, 50000): every odd 32-bit word is 0.
__global__ void detect_dtype_kernel(const int* __restrict__ ei32) {
    int nz = 0;
    for (int i = threadIdx.x; i < 512; i += blockDim.x) nz |= ei32[2 * i + 1];
    nz = __syncthreads_or(nz);
    if (threadIdx.x == 0) g_is64 = (nz == 0) ? 1 : 0;
}

__global__ void build_edges_kernel(const void* __restrict__ ei) {
    int i = blockIdx.x * blockDim.x + threadIdx.x;
    if (i >= E_TOT) return;
    int s, d;
    if (i < N_EDGES) {
        if (g_is64) {
            const long long* p = (const long long*)ei;
            s = (int)p[i];
            d = (int)p[N_EDGES + i];
        } else {
            const int* p = (const int*)ei;
            s = p[i];
            d = p[N_EDGES + i];
        }
    } else {
        s = d = i - N_EDGES;
    }
    g_src[i] = s;
    g_dst[i] = d;
    atomicAdd(&g_deg[d], 1);
}

__global__ void zero_deg_kernel() {
    int i = blockIdx.x * blockDim.x + threadIdx.x;
    if (i < N_NODES) g_deg[i] = 0;
}

// single-block exclusive scan over g_deg -> g_rowptr, g_cursor
__global__ void scan_kernel() {
    __shared__ float dummy;
    __shared__ int sh[1024];
    __shared__ int carry;
    (void)dummy;
    int tid = threadIdx.x;
    if (tid == 0) carry = 0;
    __syncthreads();
    for (int base = 0; base < N_NODES; base += 1024) {
        int idx = base + tid;
        int v = (idx < N_NODES) ? g_deg[idx] : 0;
        sh[tid] = v;
        __syncthreads();
        // Hillis-Steele inclusive scan
        #pragma unroll
        for (int off = 1; off < 1024; off <<= 1) {
            int t = (tid >= off) ? sh[tid - off] : 0;
            __syncthreads();
            sh[tid] += t;
            __syncthreads();
        }
        if (idx < N_NODES) {
            int excl = carry + sh[tid] - v;
            g_rowptr[idx] = excl;
            g_cursor[idx] = excl;
        }
        int total = sh[1023];
        __syncthreads();
        if (tid == 0) carry += total;
        __syncthreads();
    }
    if (tid == 0) g_rowptr[N_NODES] = carry;
}

__global__ void scatter_kernel() {
    int i = blockIdx.x * blockDim.x + threadIdx.x;
    if (i >= E_TOT) return;
    int d = g_dst[i];
    int pos = atomicAdd(&g_cursor[d], 1);
    g_csr_src[pos] = g_src[i];
}

// ---------------- classic 64x64 tiled SGEMM (C = A[NxK] @ B[KxM]) --------------
__global__ void sgemm_nn(const float* __restrict__ A, const float* __restrict__ B,
                         float* __restrict__ C, int N, int K, int M) {
    __shared__ float As[16][65];
    __shared__ float Bs[16][64];
    const int tx = threadIdx.x & 15;
    const int ty = threadIdx.x >> 4;
    const int n0 = blockIdx.y * 64;
    const int m0 = blockIdx.x * 64;

    float acc[4][4] = {};

    for (int k0 = 0; k0 < K; k0 += 16) {
        {
            int r = threadIdx.x >> 2;
            int c = (threadIdx.x & 3) * 4;
            int gr = n0 + r;
            float4 v = make_float4(0.f, 0.f, 0.f, 0.f);
            if (gr < N) v = *(const float4*)(A + (size_t)gr * K + k0 + c);
            As[c + 0][r] = v.x; As[c + 1][r] = v.y;
            As[c + 2][r] = v.z; As[c + 3][r] = v.w;
        }
        {
            int r = threadIdx.x >> 4;
            int c = (threadIdx.x & 15) * 4;
            float4 v = *(const float4*)(B + (size_t)(k0 + r) * M + m0 + c);
            *(float4*)&Bs[r][c] = v;
        }
        __syncthreads();

        #pragma unroll
        for (int kk = 0; kk < 16; kk++) {
            float a[4], b[4];
            #pragma unroll
            for (int i = 0; i < 4; i++) a[i] = As[kk][ty * 4 + i];
            #pragma unroll
            for (int j = 0; j < 4; j++) b[j] = Bs[kk][tx * 4 + j];
            #pragma unroll
            for (int i = 0; i < 4; i++)
                #pragma unroll
                for (int j = 0; j < 4; j++)
                    acc[i][j] += a[i] * b[j];
        }
        __syncthreads();
    }

    #pragma unroll
    for (int i = 0; i < 4; i++) {
        int gr = n0 + ty * 4 + i;
        if (gr < N) {
            #pragma unroll
            for (int j = 0; j < 4; j++)
                C[(size_t)gr * M + m0 + tx * 4 + j] = acc[i][j];
        }
    }
}

// ---------------- fused GATv2 edge kernel ---------------------------------------
// block = dst node (grid 50000), warp = head. Online softmax, no atomics.
// C: channels per head. CONCAT: layer-1 epilogue (bias+relu, concat layout)
// vs layer-2 epilogue (mean over heads + bias).
template <int C, bool CONCAT>
__global__ void __launch_bounds__(HEADS * 32)
gat_fused_kernel(const float* __restrict__ xl, const float* __restrict__ xr,
                 const float* __restrict__ att, const float* __restrict__ bias,
                 float* __restrict__ out, float* __restrict__ out2) {
    constexpr int VEC = C / 32;
    const int d    = blockIdx.x;
    const int h    = threadIdx.x >> 5;
    const int lane = threadIdx.x & 31;

    // per-lane channel slice for this head
    const size_t row_off = (size_t)h * C + lane * VEC;

    float xrv[VEC], attv[VEC];
    if constexpr (VEC == 4) {
        float4 t = *(const float4*)(xr + (size_t)d * (HEADS * C) + row_off);
        xrv[0] = t.x; xrv[1] = t.y; xrv[2] = t.z; xrv[3] = t.w;
        t = *(const float4*)(att + row_off);
        attv[0] = t.x; attv[1] = t.y; attv[2] = t.z; attv[3] = t.w;
    } else {
        xrv[0]  = xr[(size_t)d * (HEADS * C) + row_off];
        attv[0] = att[row_off];
    }

    const int row = g_rowptr[d];
    const int end = g_rowptr[d + 1];

    float M = NEG_INF, S = 0.f;
    float V[VEC];
    #pragma unroll
    for (int i = 0; i < VEC; i++) V[i] = 0.f;

    // prefetch first edge
    float xln[VEC];
    {
        int s0 = g_csr_src[row];
        const float* p = xl + (size_t)s0 * (HEADS * C) + row_off;
        if constexpr (VEC == 4) {
            float4 t = *(const float4*)p;
            xln[0] = t.x; xln[1] = t.y; xln[2] = t.z; xln[3] = t.w;
        } else {
            xln[0] = p[0];
        }
    }

    for (int e = row; e < end; e++) {
        float xlv[VEC];
        #pragma unroll
        for (int i = 0; i < VEC; i++) xlv[i] = xln[i];
        if (e + 1 < end) {
            int s2 = g_csr_src[e + 1];
            const float* p = xl + (size_t)s2 * (HEADS * C) + row_off;
            if constexpr (VEC == 4) {
                float4 t = *(const float4*)p;
                xln[0] = t.x; xln[1] = t.y; xln[2] = t.z; xln[3] = t.w;
            } else {
                xln[0] = p[0];
            }
        }

        float partial = 0.f;
        #pragma unroll
        for (int i = 0; i < VEC; i++) {
            float m = xlv[i] + xrv[i];
            partial += (m > 0.f ? m : NEG_SLOPE * m) * attv[i];
        }
        #pragma unroll
        for (int off = 16; off >= 1; off >>= 1)
            partial += __shfl_xor_sync(0xffffffffu, partial, off);
        const float esc = partial;

        const float newM  = fmaxf(M, esc);
        const float scale = __expf(M - newM);   // 0 on first edge
        const float w     = __expf(esc - newM);
        S = S * scale + w;
        #pragma unroll
        for (int i = 0; i < VEC; i++) V[i] = V[i] * scale + w * xlv[i];
        M = newM;
    }

    const float inv = 1.f / S;
    if constexpr (CONCAT) {
        // layer 1: concat heads, + bias, relu
        #pragma unroll
        for (int i = 0; i < VEC; i++) {
            float v = V[i] * inv + bias[row_off + i];
            out[(size_t)d * (HEADS * C) + row_off + i] = v > 0.f ? v : 0.f;
        }
    } else {
        // layer 2: mean over heads, + bias
        __shared__ float sh[HEADS * C];
        #pragma unroll
        for (int i = 0; i < VEC; i++) sh[row_off + i] = V[i] * inv;
        __syncthreads();
        int c = threadIdx.x;   // 128 threads, C==128
        float v = (sh[c] + sh[C + c] + sh[2 * C + c] + sh[3 * C + c]) * 0.25f
                  + bias[c];
        out[(size_t)d * C + c] = v;
        if (out2) out2[(size_t)d * C + c] = v;
    }
}

// ---------------- decoder --------------------------------------------------------
__global__ void decoder_kernel(const float* __restrict__ Wo, const float* __restrict__ bo,
                               float* __restrict__ outp) {
    int n = blockIdx.x * blockDim.x + threadIdx.x;
    if (n >= N_NODES) return;
    const float* h = g_hout + (size_t)n * C2;
    float a0 = bo[0], a1 = bo[1];
    #pragma unroll 8
    for (int c = 0; c < C2; c++) {
        float v = h[c];
        a0 += v * Wo[2 * c];
        a1 += v * Wo[2 * c + 1];
    }
    outp[2 * n + 0] = a0;
    outp[2 * n + 1] = a1;
}

// ---------------- launch ---------------------------------------------------------
static inline int cdiv(int a, int b) { return (a + b - 1) / b; }

extern "C" void kernel_launch(void* const* d_in, const int* in_sizes, int n_in,
                              void* d_out, int out_size) {
    const float* x    = (const float*)d_in[0];
    const void*  ei   = d_in[1];
    const float* Wl1  = (const float*)d_in[2];
    const float* Wr1  = (const float*)d_in[3];
    const float* att1 = (const float*)d_in[4];
    const float* b1   = (const float*)d_in[5];
    const float* Wl2  = (const float*)d_in[6];
    const float* Wr2  = (const float*)d_in[7];
    const float* att2 = (const float*)d_in[8];
    const float* b2   = (const float*)d_in[9];
    const float* Wo   = (const float*)d_in[10];
    const float* bo   = (const float*)d_in[11];

    float* outf = (float*)d_out;
    float* outp = nullptr;
    float* hp   = nullptr;
    if (out_size >= N_NODES * (OUT_DIM + C2)) { outp = outf; hp = outf + (size_t)N_NODES * OUT_DIM; }
    else if (out_size == N_NODES * C2)        { hp = outf; }
    else                                       { outp = outf; }

    float *xl1, *xr1, *h1, *xl2, *xr2, *hout;
    cudaGetSymbolAddress((void**)&xl1,  g_xl1);
    cudaGetSymbolAddress((void**)&xr1,  g_xr1);
    cudaGetSymbolAddress((void**)&h1,   g_h1);
    cudaGetSymbolAddress((void**)&xl2,  g_xl2);
    cudaGetSymbolAddress((void**)&xr2,  g_xr2);
    cudaGetSymbolAddress((void**)&hout, g_hout);

    const int T = 256;

    // 0) CSR build (by dst)
    detect_dtype_kernel<<<1, 256>>>((const int*)ei);
    zero_deg_kernel<<<cdiv(N_NODES, T), T>>>();
    build_edges_kernel<<<cdiv(E_TOT, T), T>>>(ei);
    scan_kernel<<<1, 1024>>>();
    scatter_kernel<<<cdiv(E_TOT, T), T>>>();

    // ---------------- layer 1 ----------------
    {
        dim3 g(D1 / 64, cdiv(N_NODES, 64));
        sgemm_nn<<<g, 256>>>(x, Wl1, xl1, N_NODES, F_IN, D1);
        sgemm_nn<<<g, 256>>>(x, Wr1, xr1, N_NODES, F_IN, D1);
    }
    gat_fused_kernel<C1, true><<<N_NODES, HEADS * 32>>>(xl1, xr1, att1, b1, h1, nullptr);

    // ---------------- layer 2 ----------------
    {
        dim3 g(D2 / 64, cdiv(N_NODES, 64));
        sgemm_nn<<<g, 256>>>(h1, Wl2, xl2, N_NODES, D1, D2);
        sgemm_nn<<<g, 256>>>(h1, Wr2, xr2, N_NODES, D1, D2);
    }
    gat_fused_kernel<C2, false><<<N_NODES, HEADS * 32>>>(xl2, xr2, att2, b2, hout, hp);

    if (outp) decoder_kernel<<<cdiv(N_NODES, T), T>>>(Wo, bo, outp);
}

// round 3
// speedup vs baseline: 5.3616x; 1.1820x over previous
#include <cuda_runtime.h>
#include <cuda_bf16.h>

#define N_NODES 50000
#define N_EDGES 800000
#define E_TOT   (N_EDGES + N_NODES)   // 850000 (self-loops appended)
#define F_IN    128
#define HEADS   4
#define C1      32
#define C2      128
#define D1      (HEADS * C1)          // 128
#define D2      (HEADS * C2)          // 512
#define OUT_DIM 2
#define NEG_SLOPE 0.2f
#define NEG_INF  (-3.402823466e38f)

#define SCAN_B  1024
#define SCAN_NB ((N_NODES + SCAN_B - 1) / SCAN_B)   // 49

// ---------------- device scratch (static; no cudaMalloc allowed) ---------------
__device__ float g_xl1[N_NODES * D1];
__device__ float g_xr1[N_NODES * D1];
__device__ float g_h1[N_NODES * D1];
__device__ float g_xl2[N_NODES * D2];
__device__ float g_xr2[N_NODES * D2];
__device__ int   g_src[E_TOT];
__device__ int   g_dst[E_TOT];
__device__ int   g_deg[N_NODES];
__device__ int   g_rowptr[N_NODES + 1];
__device__ int   g_cursor[N_NODES];
__device__ int   g_csr_src[E_TOT];
__device__ int   g_blocksum[SCAN_NB];
__device__ int   g_is64;

// ---------------- dtype detection for edge_index -------------------------------
__global__ void detect_dtype_kernel(const int* __restrict__ ei32) {
    int nz = 0;
    for (int i = threadIdx.x; i < 512; i += blockDim.x) nz |= ei32[2 * i + 1];
    nz = __syncthreads_or(nz);
    if (threadIdx.x == 0) g_is64 = (nz == 0) ? 1 : 0;
}

__global__ void build_edges_kernel(const void* __restrict__ ei) {
    int i = blockIdx.x * blockDim.x + threadIdx.x;
    if (i >= E_TOT) return;
    int s, d;
    if (i < N_EDGES) {
        if (g_is64) {
            const long long* p = (const long long*)ei;
            s = (int)p[i];
            d = (int)p[N_EDGES + i];
        } else {
            const int* p = (const int*)ei;
            s = p[i];
            d = p[N_EDGES + i];
        }
    } else {
        s = d = i - N_EDGES;
    }
    g_src[i] = s;
    g_dst[i] = d;
    atomicAdd(&g_deg[d], 1);
}

// ---------------- 3-phase parallel exclusive scan -------------------------------
__global__ void scan1_kernel() {
    __shared__ int sh[SCAN_B];
    const int tid = threadIdx.x;
    const int idx = blockIdx.x * SCAN_B + tid;
    int v = (idx < N_NODES) ? g_deg[idx] : 0;
    sh[tid] = v;
    __syncthreads();
    #pragma unroll
    for (int off = 1; off < SCAN_B; off <<= 1) {
        int t = (tid >= off) ? sh[tid - off] : 0;
        __syncthreads();
        sh[tid] += t;
        __syncthreads();
    }
    if (idx < N_NODES) g_rowptr[idx] = sh[tid] - v;          // block-local exclusive
    if (tid == SCAN_B - 1) g_blocksum[blockIdx.x] = sh[tid]; // block total
}

__global__ void scan2_kernel() {   // 1 block, 64 threads, scans 49 block sums
    __shared__ int sh[64];
    const int tid = threadIdx.x;
    int v = (tid < SCAN_NB) ? g_blocksum[tid] : 0;
    sh[tid] = v;
    __syncthreads();
    #pragma unroll
    for (int off = 1; off < 64; off <<= 1) {
        int t = (tid >= off) ? sh[tid - off] : 0;
        __syncthreads();
        sh[tid] += t;
        __syncthreads();
    }
    if (tid < SCAN_NB) g_blocksum[tid] = sh[tid] - v;        // exclusive
}

__global__ void scan3_kernel() {
    const int idx = blockIdx.x * blockDim.x + threadIdx.x;
    if (idx >= N_NODES) return;
    int r = g_rowptr[idx] + g_blocksum[idx / SCAN_B];
    g_rowptr[idx] = r;
    g_cursor[idx] = r;
    if (idx == 0) g_rowptr[N_NODES] = E_TOT;
}

__global__ void scatter_kernel() {
    int i = blockIdx.x * blockDim.x + threadIdx.x;
    if (i >= E_TOT) return;
    int d = g_dst[i];
    int pos = atomicAdd(&g_cursor[d], 1);
    g_csr_src[pos] = g_src[i];
}

// ---------------- 128x128 tiled, double-buffered SGEMM --------------------------
// C[N,M] = A[N,K] @ B[K,M].  K multiple of 16, M multiple of 128. N guarded.
__global__ void __launch_bounds__(256)
sgemm128(const float* __restrict__ A, const float* __restrict__ B,
         float* __restrict__ C, int N, int K, int M) {
    __shared__ float As[2][16][132];   // [buf][k][m-row], padded
    __shared__ float Bs[2][16][128];

    const int tid = threadIdx.x;
    const int tx  = tid & 15;          // 0..15 -> 8 cols each
    const int ty  = tid >> 4;          // 0..15 -> 8 rows each
    const int n0  = blockIdx.y * 128;
    const int m0  = blockIdx.x * 128;

    const int ar = tid >> 2;           // 0..63  (A rows; +64 for second half)
    const int ac = (tid & 3) * 4;      // 0,4,8,12
    const int br = tid >> 5;           // 0..7   (B k-rows; +8 for second half)
    const int bc = (tid & 31) * 4;     // 0..124

    float acc[8][8] = {};

    auto loadTiles = [&](int buf, int k0) {
        #pragma unroll
        for (int i = 0; i < 2; i++) {
            int gr = n0 + ar + i * 64;
            float4 v = make_float4(0.f, 0.f, 0.f, 0.f);
            if (gr < N) v = *(const float4*)(A + (size_t)gr * K + k0 + ac);
            As[buf][ac + 0][ar + i * 64] = v.x;
            As[buf][ac + 1][ar + i * 64] = v.y;
            As[buf][ac + 2][ar + i * 64] = v.z;
            As[buf][ac + 3][ar + i * 64] = v.w;
        }
        #pragma unroll
        for (int i = 0; i < 2; i++) {
            float4 v = *(const float4*)(B + (size_t)(k0 + br + i * 8) * M + m0 + bc);
            *(float4*)&Bs[buf][br + i * 8][bc] = v;
        }
    };

    loadTiles(0, 0);
    __syncthreads();

    const int nk = K / 16;
    for (int kt = 0; kt < nk; kt++) {
        const int buf = kt & 1;
        if (kt + 1 < nk) loadTiles(buf ^ 1, (kt + 1) * 16);

        #pragma unroll
        for (int kk = 0; kk < 16; kk++) {
            float a[8], b[8];
            *(float4*)&a[0] = *(const float4*)&As[buf][kk][ty * 8];
            *(float4*)&a[4] = *(const float4*)&As[buf][kk][ty * 8 + 4];
            *(float4*)&b[0] = *(const float4*)&Bs[buf][kk][tx * 8];
            *(float4*)&b[4] = *(const float4*)&Bs[buf][kk][tx * 8 + 4];
            #pragma unroll
            for (int i = 0; i < 8; i++)
                #pragma unroll
                for (int j = 0; j < 8; j++)
                    acc[i][j] += a[i] * b[j];
        }
        __syncthreads();
    }

    #pragma unroll
    for (int i = 0; i < 8; i++) {
        int gr = n0 + ty * 8 + i;
        if (gr < N) {
            float* cp = C + (size_t)gr * M + m0 + tx * 8;
            *(float4*)cp       = make_float4(acc[i][0], acc[i][1], acc[i][2], acc[i][3]);
            *(float4*)(cp + 4) = make_float4(acc[i][4], acc[i][5], acc[i][6], acc[i][7]);
        }
    }
}

// ---------------- fused GATv2 edge kernel ---------------------------------------
// block = dst node, warp = head. Online softmax, no atomics.
// CONCAT: layer-1 epilogue (bias+relu). Otherwise: mean-over-heads + bias,
// plus fused decoder (out @ Wo + bo) when outp != nullptr.
template <int C, bool CONCAT>
__global__ void __launch_bounds__(HEADS * 32)
gat_fused_kernel(const float* __restrict__ xl, const float* __restrict__ xr,
                 const float* __restrict__ att, const float* __restrict__ bias,
                 float* __restrict__ out, float* __restrict__ hout,
                 const float* __restrict__ Wo, const float* __restrict__ bo,
                 float* __restrict__ outp) {
    constexpr int VEC = C / 32;
    const int d    = blockIdx.x;
    const int h    = threadIdx.x >> 5;
    const int lane = threadIdx.x & 31;

    const size_t row_off = (size_t)h * C + lane * VEC;

    float xrv[VEC], attv[VEC];
    if constexpr (VEC == 4) {
        float4 t = *(const float4*)(xr + (size_t)d * (HEADS * C) + row_off);
        xrv[0] = t.x; xrv[1] = t.y; xrv[2] = t.z; xrv[3] = t.w;
        t = *(const float4*)(att + row_off);
        attv[0] = t.x; attv[1] = t.y; attv[2] = t.z; attv[3] = t.w;
    } else {
        xrv[0]  = xr[(size_t)d * (HEADS * C) + row_off];
        attv[0] = att[row_off];
    }

    const int row = g_rowptr[d];
    const int end = g_rowptr[d + 1];   // end > row guaranteed (self-loop)

    float M = NEG_INF, S = 0.f;
    float V[VEC];
    #pragma unroll
    for (int i = 0; i < VEC; i++) V[i] = 0.f;

    float xln[VEC];
    {
        int s0 = g_csr_src[row];
        const float* p = xl + (size_t)s0 * (HEADS * C) + row_off;
        if constexpr (VEC == 4) {
            float4 t = *(const float4*)p;
            xln[0] = t.x; xln[1] = t.y; xln[2] = t.z; xln[3] = t.w;
        } else {
            xln[0] = p[0];
        }
    }

    for (int e = row; e < end; e++) {
        float xlv[VEC];
        #pragma unroll
        for (int i = 0; i < VEC; i++) xlv[i] = xln[i];
        if (e + 1 < end) {
            int s2 = g_csr_src[e + 1];
            const float* p = xl + (size_t)s2 * (HEADS * C) + row_off;
            if constexpr (VEC == 4) {
                float4 t = *(const float4*)p;
                xln[0] = t.x; xln[1] = t.y; xln[2] = t.z; xln[3] = t.w;
            } else {
                xln[0] = p[0];
            }
        }

        float partial = 0.f;
        #pragma unroll
        for (int i = 0; i < VEC; i++) {
            float m = xlv[i] + xrv[i];
            partial += (m > 0.f ? m : NEG_SLOPE * m) * attv[i];
        }
        #pragma unroll
        for (int off = 16; off >= 1; off >>= 1)
            partial += __shfl_xor_sync(0xffffffffu, partial, off);
        const float esc = partial;

        const float newM  = fmaxf(M, esc);
        const float scale = __expf(M - newM);
        const float w     = __expf(esc - newM);
        S = S * scale + w;
        #pragma unroll
        for (int i = 0; i < VEC; i++) V[i] = V[i] * scale + w * xlv[i];
        M = newM;
    }

    const float inv = 1.f / S;
    if constexpr (CONCAT) {
        #pragma unroll
        for (int i = 0; i < VEC; i++) {
            float v = V[i] * inv + bias[row_off + i];
            out[(size_t)d * (HEADS * C) + row_off + i] = v > 0.f ? v : 0.f;
        }
    } else {
        __shared__ float sh[HEADS * C];
        #pragma unroll
        for (int i = 0; i < VEC; i++) sh[row_off + i] = V[i] * inv;
        __syncthreads();
        const int c = threadIdx.x;   // 128 threads, C==128
        float v = (sh[c] + sh[C + c] + sh[2 * C + c] + sh[3 * C + c]) * 0.25f
                  + bias[c];
        if (hout) hout[(size_t)d * C + c] = v;

        if (outp) {
            __shared__ float red0[128], red1[128];
            red0[c] = v * Wo[2 * c];
            red1[c] = v * Wo[2 * c + 1];
            __syncthreads();
            #pragma unroll
            for (int s = 64; s > 0; s >>= 1) {
                if (c < s) { red0[c] += red0[c + s]; red1[c] += red1[c + s]; }
                __syncthreads();
            }
            if (c == 0) {
                outp[2 * d + 0] = red0[0] + bo[0];
                outp[2 * d + 1] = red1[0] + bo[1];
            }
        }
    }
}

// ---------------- launch ---------------------------------------------------------
static inline int cdiv(int a, int b) { return (a + b - 1) / b; }

extern "C" void kernel_launch(void* const* d_in, const int* in_sizes, int n_in,
                              void* d_out, int out_size) {
    const float* x    = (const float*)d_in[0];
    const void*  ei   = d_in[1];
    const float* Wl1  = (const float*)d_in[2];
    const float* Wr1  = (const float*)d_in[3];
    const float* att1 = (const float*)d_in[4];
    const float* b1   = (const float*)d_in[5];
    const float* Wl2  = (const float*)d_in[6];
    const float* Wr2  = (const float*)d_in[7];
    const float* att2 = (const float*)d_in[8];
    const float* b2   = (const float*)d_in[9];
    const float* Wo   = (const float*)d_in[10];
    const float* bo   = (const float*)d_in[11];

    float* outf = (float*)d_out;
    float* outp = nullptr;
    float* hp   = nullptr;
    if (out_size >= N_NODES * (OUT_DIM + C2)) { outp = outf; hp = outf + (size_t)N_NODES * OUT_DIM; }
    else if (out_size == N_NODES * C2)        { hp = outf; }
    else                                       { outp = outf; }

    float *xl1, *xr1, *h1, *xl2, *xr2;
    int* degp;
    cudaGetSymbolAddress((void**)&xl1,  g_xl1);
    cudaGetSymbolAddress((void**)&xr1,  g_xr1);
    cudaGetSymbolAddress((void**)&h1,   g_h1);
    cudaGetSymbolAddress((void**)&xl2,  g_xl2);
    cudaGetSymbolAddress((void**)&xr2,  g_xr2);
    cudaGetSymbolAddress((void**)&degp, g_deg);

    const int T = 256;

    // 0) CSR build (by dst)
    detect_dtype_kernel<<<1, 256>>>((const int*)ei);
    cudaMemsetAsync(degp, 0, N_NODES * sizeof(int));
    build_edges_kernel<<<cdiv(E_TOT, T), T>>>(ei);
    scan1_kernel<<<SCAN_NB, SCAN_B>>>();
    scan2_kernel<<<1, 64>>>();
    scan3_kernel<<<cdiv(N_NODES, T), T>>>();
    scatter_kernel<<<cdiv(E_TOT, T), T>>>();

    // ---------------- layer 1 ----------------
    {
        dim3 g(D1 / 128, cdiv(N_NODES, 128));
        sgemm128<<<g, 256>>>(x, Wl1, xl1, N_NODES, F_IN, D1);
        sgemm128<<<g, 256>>>(x, Wr1, xr1, N_NODES, F_IN, D1);
    }
    gat_fused_kernel<C1, true><<<N_NODES, HEADS * 32>>>(
        xl1, xr1, att1, b1, h1, nullptr, nullptr, nullptr, nullptr);

    // ---------------- layer 2 ----------------
    {
        dim3 g(D2 / 128, cdiv(N_NODES, 128));
        sgemm128<<<g, 256>>>(h1, Wl2, xl2, N_NODES, D1, D2);
        sgemm128<<<g, 256>>>(h1, Wr2, xr2, N_NODES, D1, D2);
    }
    gat_fused_kernel<C2, false><<<N_NODES, HEADS * 32>>>(
        xl2, xr2, att2, b2, nullptr, hp, Wo, bo, outp);
}

// round 4
// speedup vs baseline: 7.0537x; 1.3156x over previous
#include <cuda_runtime.h>
#include <cuda_bf16.h>

#define N_NODES 50000
#define N_EDGES 800000
#define E_TOT   (N_EDGES + N_NODES)   // 850000 (self-loops appended)
#define F_IN    128
#define HEADS   4
#define C1      32
#define C2      128
#define D1      (HEADS * C1)          // 128
#define D2      (HEADS * C2)          // 512
#define OUT_DIM 2
#define NEG_SLOPE 0.2f
#define NEG_INF  (-3.402823466e38f)

#define SCAN_B  1024
#define SCAN_NB ((N_NODES + SCAN_B - 1) / SCAN_B)   // 49

// ---------------- device scratch (static; no cudaMalloc allowed) ---------------
__device__ float g_xl1[N_NODES * D1];
__device__ float g_xr1[N_NODES * D1];
__device__ float g_h1[N_NODES * D1];
__device__ float g_xl2[N_NODES * D2];
__device__ float g_xr2[N_NODES * D2];
__device__ int   g_src[E_TOT];
__device__ int   g_dst[E_TOT];
__device__ int   g_deg[N_NODES];
__device__ int   g_rowptr[N_NODES + 1];
__device__ int   g_cursor[N_NODES];
__device__ int   g_csr_src[E_TOT];
__device__ int   g_blocksum[SCAN_NB];
__device__ int   g_is64;

// ---------------- dtype detection for edge_index -------------------------------
__global__ void detect_dtype_kernel(const int* __restrict__ ei32) {
    int nz = 0;
    for (int i = threadIdx.x; i < 512; i += blockDim.x) nz |= ei32[2 * i + 1];
    nz = __syncthreads_or(nz);
    if (threadIdx.x == 0) g_is64 = (nz == 0) ? 1 : 0;
}

__global__ void build_edges_kernel(const void* __restrict__ ei) {
    int i = blockIdx.x * blockDim.x + threadIdx.x;
    if (i >= E_TOT) return;
    int s, d;
    if (i < N_EDGES) {
        if (g_is64) {
            const long long* p = (const long long*)ei;
            s = (int)p[i];
            d = (int)p[N_EDGES + i];
        } else {
            const int* p = (const int*)ei;
            s = p[i];
            d = p[N_EDGES + i];
        }
    } else {
        s = d = i - N_EDGES;
    }
    g_src[i] = s;
    g_dst[i] = d;
    atomicAdd(&g_deg[d], 1);
}

// ---------------- 3-phase parallel exclusive scan -------------------------------
__global__ void scan1_kernel() {
    __shared__ int sh[SCAN_B];
    const int tid = threadIdx.x;
    const int idx = blockIdx.x * SCAN_B + tid;
    int v = (idx < N_NODES) ? g_deg[idx] : 0;
    sh[tid] = v;
    __syncthreads();
    #pragma unroll
    for (int off = 1; off < SCAN_B; off <<= 1) {
        int t = (tid >= off) ? sh[tid - off] : 0;
        __syncthreads();
        sh[tid] += t;
        __syncthreads();
    }
    if (idx < N_NODES) g_rowptr[idx] = sh[tid] - v;
    if (tid == SCAN_B - 1) g_blocksum[blockIdx.x] = sh[tid];
}

__global__ void scan2_kernel() {
    __shared__ int sh[64];
    const int tid = threadIdx.x;
    int v = (tid < SCAN_NB) ? g_blocksum[tid] : 0;
    sh[tid] = v;
    __syncthreads();
    #pragma unroll
    for (int off = 1; off < 64; off <<= 1) {
        int t = (tid >= off) ? sh[tid - off] : 0;
        __syncthreads();
        sh[tid] += t;
        __syncthreads();
    }
    if (tid < SCAN_NB) g_blocksum[tid] = sh[tid] - v;
}

__global__ void scan3_kernel() {
    const int idx = blockIdx.x * blockDim.x + threadIdx.x;
    if (idx >= N_NODES) return;
    int r = g_rowptr[idx] + g_blocksum[idx / SCAN_B];
    g_rowptr[idx] = r;
    g_cursor[idx] = r;
    if (idx == 0) g_rowptr[N_NODES] = E_TOT;
}

__global__ void scatter_kernel() {
    int i = blockIdx.x * blockDim.x + threadIdx.x;
    if (i >= E_TOT) return;
    int d = g_dst[i];
    int pos = atomicAdd(&g_cursor[d], 1);
    g_csr_src[pos] = g_src[i];
}

// ---------------- TF32 tensor-core GEMM -----------------------------------------
// C[N,M] = A[N,K] @ B[K,M], fp32 in/out, tf32 mma (m16n8k8), fp32 accumulate.
// BM=128, BN=128, BK=16, 8 warps: warp (wm,wn) owns 64x32. K % 16 == 0,
// M % 128 == 0, N guarded.
#define TFS 136   // smem row stride (words): banks (8*tig + group) conflict-free

__device__ __forceinline__ unsigned f2tf32(float f) {
    unsigned r;
    asm("cvt.rna.tf32.f32 %0, %1;" : "=r"(r) : "f"(f));
    return r;
}

__device__ __forceinline__ void mma_tf32(float* d, const unsigned* a, const unsigned* b) {
    asm volatile(
        "mma.sync.aligned.m16n8k8.row.col.f32.tf32.tf32.f32 "
        "{%0,%1,%2,%3}, {%4,%5,%6,%7}, {%8,%9}, {%0,%1,%2,%3};"
        : "+f"(d[0]), "+f"(d[1]), "+f"(d[2]), "+f"(d[3])
        : "r"(a[0]), "r"(a[1]), "r"(a[2]), "r"(a[3]), "r"(b[0]), "r"(b[1]));
}

__global__ void __launch_bounds__(256)
sgemm_tf32(const float* __restrict__ A, const float* __restrict__ B,
           float* __restrict__ C, int N, int K, int M) {
    __shared__ unsigned As[2][16][TFS];  // [buf][k][m]  (A transposed)
    __shared__ unsigned Bs[2][16][TFS];  // [buf][k][n]

    const int tid  = threadIdx.x;
    const int wid  = tid >> 5;
    const int lane = tid & 31;
    const int grp  = lane >> 2;    // 0..7
    const int tig  = lane & 3;     // 0..3
    const int wm   = wid >> 2;     // 0..1 -> 64 rows
    const int wn   = wid & 3;      // 0..3 -> 32 cols
    const int n0   = blockIdx.y * 128;
    const int m0   = blockIdx.x * 128;

    float acc[4][4][4] = {};       // [mi][ni][frag]

    auto loadTiles = [&](int buf, int k0) {
        // A: 128 rows x 16 k-cols -> As[k][m] (transposed, tf32)
        #pragma unroll
        for (int p = 0; p < 2; p++) {
            int idx = p * 256 + tid;
            int row = idx >> 2;            // 0..127
            int c4  = (idx & 3) * 4;       // 0,4,8,12
            int gr  = n0 + row;
            float4 v = make_float4(0.f, 0.f, 0.f, 0.f);
            if (gr < N) v = *(const float4*)(A + (size_t)gr * K + k0 + c4);
            As[buf][c4 + 0][row] = f2tf32(v.x);
            As[buf][c4 + 1][row] = f2tf32(v.y);
            As[buf][c4 + 2][row] = f2tf32(v.z);
            As[buf][c4 + 3][row] = f2tf32(v.w);
        }
        // B: 16 k-rows x 128 n-cols -> Bs[k][n]
        #pragma unroll
        for (int p = 0; p < 2; p++) {
            int idx = p * 256 + tid;
            int r = idx >> 5;              // 0..15
            int c = (idx & 31) * 4;        // 0..124
            float4 v = *(const float4*)(B + (size_t)(k0 + r) * M + m0 + c);
            Bs[buf][r][c + 0] = f2tf32(v.x);
            Bs[buf][r][c + 1] = f2tf32(v.y);
            Bs[buf][r][c + 2] = f2tf32(v.z);
            Bs[buf][r][c + 3] = f2tf32(v.w);
        }
    };

    loadTiles(0, 0);
    __syncthreads();

    const int nk = K / 16;
    for (int kt = 0; kt < nk; kt++) {
        const int buf = kt & 1;
        if (kt + 1 < nk) loadTiles(buf ^ 1, (kt + 1) * 16);

        #pragma unroll
        for (int kk = 0; kk < 2; kk++) {
            const int kb = kk * 8;
            unsigned af[4][4], bf[4][2];
            #pragma unroll
            for (int mi = 0; mi < 4; mi++) {
                int rb = wm * 64 + mi * 16 + grp;
                af[mi][0] = As[buf][kb + tig    ][rb];
                af[mi][1] = As[buf][kb + tig    ][rb + 8];
                af[mi][2] = As[buf][kb + tig + 4][rb];
                af[mi][3] = As[buf][kb + tig + 4][rb + 8];
            }
            #pragma unroll
            for (int ni = 0; ni < 4; ni++) {
                int nb = wn * 32 + ni * 8 + grp;
                bf[ni][0] = Bs[buf][kb + tig    ][nb];
                bf[ni][1] = Bs[buf][kb + tig + 4][nb];
            }
            #pragma unroll
            for (int mi = 0; mi < 4; mi++)
                #pragma unroll
                for (int ni = 0; ni < 4; ni++)
                    mma_tf32(acc[mi][ni], af[mi], bf[ni]);
        }
        __syncthreads();
    }

    // epilogue: c0,c1 adjacent cols (2*tig, 2*tig+1) -> float2 stores
    #pragma unroll
    for (int mi = 0; mi < 4; mi++) {
        int r0 = n0 + wm * 64 + mi * 16 + grp;
        int r1 = r0 + 8;
        #pragma unroll
        for (int ni = 0; ni < 4; ni++) {
            int col = m0 + wn * 32 + ni * 8 + tig * 2;
            if (r0 < N)
                *(float2*)(C + (size_t)r0 * M + col) = make_float2(acc[mi][ni][0], acc[mi][ni][1]);
            if (r1 < N)
                *(float2*)(C + (size_t)r1 * M + col) = make_float2(acc[mi][ni][2], acc[mi][ni][3]);
        }
    }
}

// ---------------- fused GATv2 edge kernel ---------------------------------------
template <int C, bool CONCAT>
__global__ void __launch_bounds__(HEADS * 32)
gat_fused_kernel(const float* __restrict__ xl, const float* __restrict__ xr,
                 const float* __restrict__ att, const float* __restrict__ bias,
                 float* __restrict__ out, float* __restrict__ hout,
                 const float* __restrict__ Wo, const float* __restrict__ bo,
                 float* __restrict__ outp) {
    constexpr int VEC = C / 32;
    const int d    = blockIdx.x;
    const int h    = threadIdx.x >> 5;
    const int lane = threadIdx.x & 31;

    const size_t row_off = (size_t)h * C + lane * VEC;

    float xrv[VEC], attv[VEC];
    if constexpr (VEC == 4) {
        float4 t = *(const float4*)(xr + (size_t)d * (HEADS * C) + row_off);
        xrv[0] = t.x; xrv[1] = t.y; xrv[2] = t.z; xrv[3] = t.w;
        t = *(const float4*)(att + row_off);
        attv[0] = t.x; attv[1] = t.y; attv[2] = t.z; attv[3] = t.w;
    } else {
        xrv[0]  = xr[(size_t)d * (HEADS * C) + row_off];
        attv[0] = att[row_off];
    }

    const int row = g_rowptr[d];
    const int end = g_rowptr[d + 1];

    float M = NEG_INF, S = 0.f;
    float V[VEC];
    #pragma unroll
    for (int i = 0; i < VEC; i++) V[i] = 0.f;

    float xln[VEC];
    {
        int s0 = g_csr_src[row];
        const float* p = xl + (size_t)s0 * (HEADS * C) + row_off;
        if constexpr (VEC == 4) {
            float4 t = *(const float4*)p;
            xln[0] = t.x; xln[1] = t.y; xln[2] = t.z; xln[3] = t.w;
        } else {
            xln[0] = p[0];
        }
    }

    for (int e = row; e < end; e++) {
        float xlv[VEC];
        #pragma unroll
        for (int i = 0; i < VEC; i++) xlv[i] = xln[i];
        if (e + 1 < end) {
            int s2 = g_csr_src[e + 1];
            const float* p = xl + (size_t)s2 * (HEADS * C) + row_off;
            if constexpr (VEC == 4) {
                float4 t = *(const float4*)p;
                xln[0] = t.x; xln[1] = t.y; xln[2] = t.z; xln[3] = t.w;
            } else {
                xln[0] = p[0];
            }
        }

        float partial = 0.f;
        #pragma unroll
        for (int i = 0; i < VEC; i++) {
            float m = xlv[i] + xrv[i];
            partial += (m > 0.f ? m : NEG_SLOPE * m) * attv[i];
        }
        #pragma unroll
        for (int off = 16; off >= 1; off >>= 1)
            partial += __shfl_xor_sync(0xffffffffu, partial, off);
        const float esc = partial;

        const float newM  = fmaxf(M, esc);
        const float scale = __expf(M - newM);
        const float w     = __expf(esc - newM);
        S = S * scale + w;
        #pragma unroll
        for (int i = 0; i < VEC; i++) V[i] = V[i] * scale + w * xlv[i];
        M = newM;
    }

    const float inv = 1.f / S;
    if constexpr (CONCAT) {
        #pragma unroll
        for (int i = 0; i < VEC; i++) {
            float v = V[i] * inv + bias[row_off + i];
            out[(size_t)d * (HEADS * C) + row_off + i] = v > 0.f ? v : 0.f;
        }
    } else {
        __shared__ float sh[HEADS * C];
        #pragma unroll
        for (int i = 0; i < VEC; i++) sh[row_off + i] = V[i] * inv;
        __syncthreads();
        const int c = threadIdx.x;   // 128 threads, C==128
        float v = (sh[c] + sh[C + c] + sh[2 * C + c] + sh[3 * C + c]) * 0.25f
                  + bias[c];
        if (hout) hout[(size_t)d * C + c] = v;

        if (outp) {
            __shared__ float red0[128], red1[128];
            red0[c] = v * Wo[2 * c];
            red1[c] = v * Wo[2 * c + 1];
            __syncthreads();
            #pragma unroll
            for (int s = 64; s > 0; s >>= 1) {
                if (c < s) { red0[c] += red0[c + s]; red1[c] += red1[c + s]; }
                __syncthreads();
            }
            if (c == 0) {
                outp[2 * d + 0] = red0[0] + bo[0];
                outp[2 * d + 1] = red1[0] + bo[1];
            }
        }
    }
}

// ---------------- launch ---------------------------------------------------------
static inline int cdiv(int a, int b) { return (a + b - 1) / b; }

extern "C" void kernel_launch(void* const* d_in, const int* in_sizes, int n_in,
                              void* d_out, int out_size) {
    const float* x    = (const float*)d_in[0];
    const void*  ei   = d_in[1];
    const float* Wl1  = (const float*)d_in[2];
    const float* Wr1  = (const float*)d_in[3];
    const float* att1 = (const float*)d_in[4];
    const float* b1   = (const float*)d_in[5];
    const float* Wl2  = (const float*)d_in[6];
    const float* Wr2  = (const float*)d_in[7];
    const float* att2 = (const float*)d_in[8];
    const float* b2   = (const float*)d_in[9];
    const float* Wo   = (const float*)d_in[10];
    const float* bo   = (const float*)d_in[11];

    float* outf = (float*)d_out;
    float* outp = nullptr;
    float* hp   = nullptr;
    if (out_size >= N_NODES * (OUT_DIM + C2)) { outp = outf; hp = outf + (size_t)N_NODES * OUT_DIM; }
    else if (out_size == N_NODES * C2)        { hp = outf; }
    else                                       { outp = outf; }

    float *xl1, *xr1, *h1, *xl2, *xr2;
    int* degp;
    cudaGetSymbolAddress((void**)&xl1,  g_xl1);
    cudaGetSymbolAddress((void**)&xr1,  g_xr1);
    cudaGetSymbolAddress((void**)&h1,   g_h1);
    cudaGetSymbolAddress((void**)&xl2,  g_xl2);
    cudaGetSymbolAddress((void**)&xr2,  g_xr2);
    cudaGetSymbolAddress((void**)&degp, g_deg);

    const int T = 256;

    // 0) CSR build (by dst)
    detect_dtype_kernel<<<1, 256>>>((const int*)ei);
    cudaMemsetAsync(degp, 0, N_NODES * sizeof(int));
    build_edges_kernel<<<cdiv(E_TOT, T), T>>>(ei);
    scan1_kernel<<<SCAN_NB, SCAN_B>>>();
    scan2_kernel<<<1, 64>>>();
    scan3_kernel<<<cdiv(N_NODES, T), T>>>();
    scatter_kernel<<<cdiv(E_TOT, T), T>>>();

    // ---------------- layer 1 ----------------
    {
        dim3 g(D1 / 128, cdiv(N_NODES, 128));
        sgemm_tf32<<<g, 256>>>(x, Wl1, xl1, N_NODES, F_IN, D1);
        sgemm_tf32<<<g, 256>>>(x, Wr1, xr1, N_NODES, F_IN, D1);
    }
    gat_fused_kernel<C1, true><<<N_NODES, HEADS * 32>>>(
        xl1, xr1, att1, b1, h1, nullptr, nullptr, nullptr, nullptr);

    // ---------------- layer 2 ----------------
    {
        dim3 g(D2 / 128, cdiv(N_NODES, 128));
        sgemm_tf32<<<g, 256>>>(h1, Wl2, xl2, N_NODES, D1, D2);
        sgemm_tf32<<<g, 256>>>(h1, Wr2, xr2, N_NODES, D1, D2);
    }
    gat_fused_kernel<C2, false><<<N_NODES, HEADS * 32>>>(
        xl2, xr2, att2, b2, nullptr, hp, Wo, bo, outp);
}